// round 8
// baseline (speedup 1.0000x reference)
#include <cuda_runtime.h>
#include <cuda_bf16.h>
#include <cstdint>

#define C1_IN 8
#define NN 16384

__device__ float g_h[NN * 64];

__device__ __forceinline__ int clamp_idx(int v, int n) {
    v = v < 0 ? 0 : v;
    return v >= n ? n - 1 : v;
}

__device__ __forceinline__ unsigned long long pk2(float lo, float hi) {
    unsigned long long r;
    asm("mov.b64 %0, {%1, %2};" : "=l"(r) : "f"(lo), "f"(hi));
    return r;
}
__device__ __forceinline__ void upk2(unsigned long long v, float& lo, float& hi) {
    asm("mov.b64 {%0, %1}, %2;" : "=f"(lo), "=f"(hi) : "l"(v));
}
__device__ __forceinline__ unsigned long long ffma2(unsigned long long a,
                                                    unsigned long long b,
                                                    unsigned long long c) {
    unsigned long long d;
    asm("fma.rn.f32x2 %0, %1, %2, %3;" : "=l"(d) : "l"(a), "l"(b), "l"(c));
    return d;
}
__device__ __forceinline__ unsigned long long relu2(unsigned long long v) {
    float lo, hi;
    upk2(v, lo, hi);
    return pk2(fmaxf(lo, 0.0f), fmaxf(hi, 0.0f));
}

// ---------------------------------------------------------------------------
// K1: h[n,o] = sum_i x[n,i] * root1[i,o] + bias1[o]
// ---------------------------------------------------------------------------
__global__ void k_node1(const float* __restrict__ x,
                        const float* __restrict__ root1,
                        const float* __restrict__ bias1,
                        int N)
{
    int idx = blockIdx.x * blockDim.x + threadIdx.x;
    if (idx >= N * 64) return;
    int n = idx >> 6;
    int o = idx & 63;
    const float* xr = x + n * C1_IN;
    float acc = __ldg(&bias1[o]);
#pragma unroll
    for (int i = 0; i < C1_IN; i++)
        acc = fmaf(__ldg(&xr[i]), __ldg(&root1[i * 64 + o]), acc);
    g_h[idx] = acc;
}

// ---------------------------------------------------------------------------
// K2: layer-1 edge kernel. Warp-autonomous; lane owns cols (2l, 2l+1),
// packed f32x2 weights AND packed accumulator. No smem, no barriers.
// ---------------------------------------------------------------------------
__global__ __launch_bounds__(256)
void k_edge1(const float* __restrict__ x,
             const int* __restrict__ ei,
             const float* __restrict__ ea,
             const float* __restrict__ A1,
             const float* __restrict__ b1,
             int E, int N)
{
    const int lane = threadIdx.x & 31;
    const int c0 = 2 * lane;

    unsigned long long A0p[8], A1p[8], Bp[8];
#pragma unroll
    for (int k = 0; k < 8; k++) {
        A0p[k] = pk2(__ldg(&A1[k * 64 + c0]),       __ldg(&A1[k * 64 + c0 + 1]));
        A1p[k] = pk2(__ldg(&A1[512 + k * 64 + c0]), __ldg(&A1[512 + k * 64 + c0 + 1]));
        Bp[k]  = pk2(__ldg(&b1[k * 64 + c0]),       __ldg(&b1[k * 64 + c0 + 1]));
    }

    const int gw = (blockIdx.x * blockDim.x + threadIdx.x) >> 5;
    const int nw = (gridDim.x * blockDim.x) >> 5;

    for (int e = gw; e < E; e += nw) {
        int src = clamp_idx(__ldg(&ei[e]), N);
        int dst = clamp_idx(__ldg(&ei[E + e]), N);
        float2 a = __ldg(reinterpret_cast<const float2*>(ea) + e);
        unsigned long long a0p = pk2(a.x, a.x);
        unsigned long long a1p = pk2(a.y, a.y);

        float xv = (lane < C1_IN) ? __ldg(&x[src * C1_IN + lane]) : 0.0f;

        unsigned long long acc2 = 0ull;
#pragma unroll
        for (int k = 0; k < 8; k++) {
            float xk = __shfl_sync(0xffffffffu, xv, k);
            unsigned long long w = ffma2(a1p, A1p[k], ffma2(a0p, A0p[k], Bp[k]));
            acc2 = ffma2(relu2(w), pk2(xk, xk), acc2);
        }
        float acc0, acc1;
        upk2(acc2, acc0, acc1);
        float* p = g_h + (size_t)dst * 64 + c0;
        asm volatile("red.global.add.v2.f32 [%0], {%1, %2};"
                     :: "l"(p), "f"(acc0), "f"(acc1) : "memory");
    }
}

// ---------------------------------------------------------------------------
// K3: out[n,o] = sum_i h[n,i] * root2[i,o] + bias2[o]
// ---------------------------------------------------------------------------
__global__ __launch_bounds__(256)
void k_node2(const float* __restrict__ root2,
             const float* __restrict__ bias2,
             float* __restrict__ out,
             int N)
{
    __shared__ __align__(16) float r2[4096];
    for (int i = threadIdx.x; i < 4096; i += blockDim.x)
        r2[i] = root2[i];
    __syncthreads();

    const int op = threadIdx.x & 31;   // col pair: cols (2*op, 2*op+1)
    const int j  = threadIdx.x >> 5;   // 0..7
    float2 bv = __ldg(reinterpret_cast<const float2*>(bias2) + op);
    const unsigned long long bp = pk2(bv.x, bv.y);
    const unsigned long long* r2p = reinterpret_cast<const unsigned long long*>(r2);

    for (int nb = blockIdx.x * 8; nb < N; nb += gridDim.x * 8) {
        int n = nb + j;
        const float4* hr = reinterpret_cast<const float4*>(g_h + (size_t)n * 64);
        unsigned long long acc = bp;
#pragma unroll
        for (int q = 0; q < 16; q++) {
            float4 hv = hr[q];
            acc = ffma2(pk2(hv.x, hv.x), r2p[(q * 4 + 0) * 32 + op], acc);
            acc = ffma2(pk2(hv.y, hv.y), r2p[(q * 4 + 1) * 32 + op], acc);
            acc = ffma2(pk2(hv.z, hv.z), r2p[(q * 4 + 2) * 32 + op], acc);
            acc = ffma2(pk2(hv.w, hv.w), r2p[(q * 4 + 3) * 32 + op], acc);
        }
        float ol, oh;
        upk2(acc, ol, oh);
        float2* po = reinterpret_cast<float2*>(out + (size_t)n * 64) + op;
        *po = make_float2(ol, oh);
    }
}

// ---------------------------------------------------------------------------
// K4: layer-2 edge kernel (the heavy one).
// Block = 256 threads = 8 warps. Warp w owns cols [w*8, w*8+8).
// Thread = (col = w*8 + (lane&7), k-quarter kq = lane>>3):
//   k in [kq*16, kq*16+16) as 8 packed k-pairs -> 48 weight regs.
// Packed f32x2 W-eval AND packed accumulator; h read as LDS.128.
// Double-buffered gather; ONE barrier per 8-edge batch.
// Cross-k reduce = shfl_xor(8) + shfl_xor(16); scatter = predicated red.
// ---------------------------------------------------------------------------
#define EPB 8

__global__ __launch_bounds__(256, 3)
void k_edge2(const int* __restrict__ ei,
             const float* __restrict__ ea,
             const float* __restrict__ A2,
             const float* __restrict__ b2,
             float* __restrict__ out,
             int E, int N)
{
    const int tid  = threadIdx.x;
    const int warp = tid >> 5;
    const int lane = tid & 31;
    const int col  = warp * 8 + (lane & 7);
    const int kq   = lane >> 3;        // 0..3
    const int kbase = kq * 16;

    // Weight cache: 8 packed k-pairs for this (col, kq) slice.
    unsigned long long A0p[8], A1p[8], Bp[8];
#pragma unroll
    for (int kk = 0; kk < 8; kk++) {
        int k0 = kbase + 2 * kk;
        A0p[kk] = pk2(__ldg(&A2[k0 * 64 + col]),        __ldg(&A2[(k0 + 1) * 64 + col]));
        A1p[kk] = pk2(__ldg(&A2[4096 + k0 * 64 + col]), __ldg(&A2[4096 + (k0 + 1) * 64 + col]));
        Bp[kk]  = pk2(__ldg(&b2[k0 * 64 + col]),        __ldg(&b2[(k0 + 1) * 64 + col]));
    }

    __shared__ __align__(16) float hs[2][EPB][64];
    __shared__ float sA0[2][EPB];
    __shared__ float sA1[2][EPB];
    __shared__ int   sDst[2][EPB];

    const int nbatch = (E + EPB - 1) / EPB;

    auto load_batch = [&](int b, int buf) {
        if (tid < 128) {
            int gj = tid >> 4, gq = tid & 15;
            int e = b * EPB + gj;
            int src = 0;
            if (e < E) src = clamp_idx(__ldg(&ei[e]), N);
            reinterpret_cast<float4*>(&hs[buf][gj][0])[gq] =
                reinterpret_cast<const float4*>(g_h + (size_t)src * 64)[gq];
        } else if (tid < 128 + EPB) {
            int t = tid - 128;
            int em = b * EPB + t;
            float a0 = 0.0f, a1 = 0.0f;
            int dst = 0;
            if (em < E) {
                float2 a = __ldg(reinterpret_cast<const float2*>(ea) + em);
                a0 = a.x; a1 = a.y;
                dst = clamp_idx(__ldg(&ei[E + em]), N);
            }
            sA0[buf][t] = a0;
            sA1[buf][t] = a1;
            sDst[buf][t] = dst;
        }
    };

    int b = blockIdx.x;
    int buf = 0;
    if (b < nbatch) load_batch(b, 0);
    __syncthreads();

    while (b < nbatch) {
        int bn = b + gridDim.x;
        if (bn < nbatch) load_batch(bn, buf ^ 1);

        int e0 = b * EPB;
#pragma unroll 2
        for (int j = 0; j < EPB; j++) {
            float a0 = sA0[buf][j];
            float a1 = sA1[buf][j];
            unsigned long long a0p = pk2(a0, a0);
            unsigned long long a1p = pk2(a1, a1);
            const ulonglong2* hp =
                reinterpret_cast<const ulonglong2*>(&hs[buf][j][kbase]);

            unsigned long long acc2 = 0ull;
#pragma unroll
            for (int t = 0; t < 4; t++) {
                ulonglong2 hv = hp[t];  // 2 packed k-pairs, LDS.128 broadcast
                {
                    unsigned long long w =
                        ffma2(a1p, A1p[2 * t], ffma2(a0p, A0p[2 * t], Bp[2 * t]));
                    acc2 = ffma2(relu2(w), hv.x, acc2);
                }
                {
                    unsigned long long w =
                        ffma2(a1p, A1p[2 * t + 1], ffma2(a0p, A0p[2 * t + 1], Bp[2 * t + 1]));
                    acc2 = ffma2(relu2(w), hv.y, acc2);
                }
            }
            float al, ah;
            upk2(acc2, al, ah);
            float acc = al + ah;
            // reduce across the 4 k-quarters (lane bits 3 and 4)
            acc += __shfl_xor_sync(0xffffffffu, acc, 8);
            acc += __shfl_xor_sync(0xffffffffu, acc, 16);
            if (kq == 0 && (e0 + j) < E) {
                float* p = out + (size_t)sDst[buf][j] * 64 + col;
                asm volatile("red.global.add.f32 [%0], %1;"
                             :: "l"(p), "f"(acc) : "memory");
            }
        }
        __syncthreads();
        buf ^= 1;
        b = bn;
    }
}

// ---------------------------------------------------------------------------
// Launch
// ---------------------------------------------------------------------------
extern "C" void kernel_launch(void* const* d_in, const int* in_sizes, int n_in,
                              void* d_out, int out_size)
{
    const float* x     = (const float*)d_in[0];
    const int*   ei    = (const int*)d_in[1];
    const float* ea    = (const float*)d_in[2];
    const float* A1    = (const float*)d_in[3];
    const float* b1    = (const float*)d_in[4];
    const float* A2    = (const float*)d_in[5];
    const float* b2    = (const float*)d_in[6];
    const float* root1 = (const float*)d_in[7];
    const float* bias1 = (const float*)d_in[8];
    const float* root2 = (const float*)d_in[9];
    const float* bias2 = (const float*)d_in[10];
    float* out = (float*)d_out;

    const int N = in_sizes[0] / C1_IN;   // 16384
    const int E = in_sizes[1] / 2;       // 65536

    {
        int total = N * 64;
        int blocks = (total + 255) / 256;
        k_node1<<<blocks, 256>>>(x, root1, bias1, N);
    }
    k_edge1<<<888, 256>>>(x, ei, ea, A1, b1, E, N);
    k_node2<<<512, 256>>>(root2, bias2, out, N);
    k_edge2<<<444, 256>>>(ei, ea, A2, b2, out, E, N);
}

// round 10
// speedup vs baseline: 1.0529x; 1.0529x over previous
#include <cuda_runtime.h>
#include <cuda_bf16.h>
#include <cstdint>

#define C1_IN 8
#define NN 16384

__device__ float g_h[NN * 64];

__device__ __forceinline__ int clamp_idx(int v, int n) {
    v = v < 0 ? 0 : v;
    return v >= n ? n - 1 : v;
}

__device__ __forceinline__ unsigned long long pk2(float lo, float hi) {
    unsigned long long r;
    asm("mov.b64 %0, {%1, %2};" : "=l"(r) : "f"(lo), "f"(hi));
    return r;
}
__device__ __forceinline__ void upk2(unsigned long long v, float& lo, float& hi) {
    asm("mov.b64 {%0, %1}, %2;" : "=f"(lo), "=f"(hi) : "l"(v));
}
__device__ __forceinline__ unsigned long long ffma2(unsigned long long a,
                                                    unsigned long long b,
                                                    unsigned long long c) {
    unsigned long long d;
    asm("fma.rn.f32x2 %0, %1, %2, %3;" : "=l"(d) : "l"(a), "l"(b), "l"(c));
    return d;
}
__device__ __forceinline__ unsigned long long relu2(unsigned long long v) {
    float lo, hi;
    upk2(v, lo, hi);
    return pk2(fmaxf(lo, 0.0f), fmaxf(hi, 0.0f));
}

// ---------------------------------------------------------------------------
// K1: h[n,o] = sum_i x[n,i] * root1[i,o] + bias1[o]
// ---------------------------------------------------------------------------
__global__ void k_node1(const float* __restrict__ x,
                        const float* __restrict__ root1,
                        const float* __restrict__ bias1,
                        int N)
{
    int idx = blockIdx.x * blockDim.x + threadIdx.x;
    if (idx >= N * 64) return;
    int n = idx >> 6;
    int o = idx & 63;
    const float* xr = x + n * C1_IN;
    float acc = __ldg(&bias1[o]);
#pragma unroll
    for (int i = 0; i < C1_IN; i++)
        acc = fmaf(__ldg(&xr[i]), __ldg(&root1[i * 64 + o]), acc);
    g_h[idx] = acc;
}

// ---------------------------------------------------------------------------
// K2: layer-1 edge kernel. Warp-autonomous; lane owns cols (2l, 2l+1).
// Packed weights + packed accumulator. 2 edges per iteration for ILP.
// ---------------------------------------------------------------------------
__global__ __launch_bounds__(256)
void k_edge1(const float* __restrict__ x,
             const int* __restrict__ ei,
             const float* __restrict__ ea,
             const float* __restrict__ A1,
             const float* __restrict__ b1,
             int E, int N)
{
    const int lane = threadIdx.x & 31;
    const int c0 = 2 * lane;

    unsigned long long A0p[8], A1p[8], Bp[8];
#pragma unroll
    for (int k = 0; k < 8; k++) {
        A0p[k] = pk2(__ldg(&A1[k * 64 + c0]),       __ldg(&A1[k * 64 + c0 + 1]));
        A1p[k] = pk2(__ldg(&A1[512 + k * 64 + c0]), __ldg(&A1[512 + k * 64 + c0 + 1]));
        Bp[k]  = pk2(__ldg(&b1[k * 64 + c0]),       __ldg(&b1[k * 64 + c0 + 1]));
    }

    const int gw = (blockIdx.x * blockDim.x + threadIdx.x) >> 5;
    const int nw = (gridDim.x * blockDim.x) >> 5;

    for (int e0 = gw * 2; e0 < E; e0 += nw * 2) {
#pragma unroll
        for (int u = 0; u < 2; u++) {
            int e = e0 + u;
            if (e >= E) break;
            int src = clamp_idx(__ldg(&ei[e]), N);
            int dst = clamp_idx(__ldg(&ei[E + e]), N);
            float2 a = __ldg(reinterpret_cast<const float2*>(ea) + e);
            unsigned long long a0p = pk2(a.x, a.x);
            unsigned long long a1p = pk2(a.y, a.y);

            float xv = (lane < C1_IN) ? __ldg(&x[src * C1_IN + lane]) : 0.0f;

            unsigned long long acc2 = 0ull;
#pragma unroll
            for (int k = 0; k < 8; k++) {
                float xk = __shfl_sync(0xffffffffu, xv, k);
                unsigned long long w = ffma2(a1p, A1p[k], ffma2(a0p, A0p[k], Bp[k]));
                acc2 = ffma2(relu2(w), pk2(xk, xk), acc2);
            }
            float acc0, acc1;
            upk2(acc2, acc0, acc1);
            float* p = g_h + (size_t)dst * 64 + c0;
            asm volatile("red.global.add.v2.f32 [%0], {%1, %2};"
                         :: "l"(p), "f"(acc0), "f"(acc1) : "memory");
        }
    }
}

// ---------------------------------------------------------------------------
// K3: out[n,o] = sum_i h[n,i] * root2[i,o] + bias2[o]
// ---------------------------------------------------------------------------
__global__ __launch_bounds__(256)
void k_node2(const float* __restrict__ root2,
             const float* __restrict__ bias2,
             float* __restrict__ out,
             int N)
{
    __shared__ __align__(16) float r2[4096];
    for (int i = threadIdx.x; i < 4096; i += blockDim.x)
        r2[i] = root2[i];
    __syncthreads();

    const int op = threadIdx.x & 31;   // col pair: cols (2*op, 2*op+1)
    const int j  = threadIdx.x >> 5;   // 0..7
    float2 bv = __ldg(reinterpret_cast<const float2*>(bias2) + op);
    const unsigned long long bp = pk2(bv.x, bv.y);
    const unsigned long long* r2p = reinterpret_cast<const unsigned long long*>(r2);

    for (int nb = blockIdx.x * 8; nb < N; nb += gridDim.x * 8) {
        int n = nb + j;
        const float4* hr = reinterpret_cast<const float4*>(g_h + (size_t)n * 64);
        unsigned long long acc = bp;
#pragma unroll
        for (int q = 0; q < 16; q++) {
            float4 hv = hr[q];
            acc = ffma2(pk2(hv.x, hv.x), r2p[(q * 4 + 0) * 32 + op], acc);
            acc = ffma2(pk2(hv.y, hv.y), r2p[(q * 4 + 1) * 32 + op], acc);
            acc = ffma2(pk2(hv.z, hv.z), r2p[(q * 4 + 2) * 32 + op], acc);
            acc = ffma2(pk2(hv.w, hv.w), r2p[(q * 4 + 3) * 32 + op], acc);
        }
        float ol, oh;
        upk2(acc, ol, oh);
        float2* po = reinterpret_cast<float2*>(out + (size_t)n * 64) + op;
        *po = make_float2(ol, oh);
    }
}

// ---------------------------------------------------------------------------
// K4: layer-2 edge kernel (the heavy one).
// Block = 128 threads = 4 warps. Warp w owns cols [w*16, w*16+16).
// Thread = (col = w*16 + (lane&15), k-half g = lane>>4), k in [g*32,+32)
// as 16 packed k-pairs (96 weight regs). Packed W-eval AND packed acc;
// h read as LDS.128 (ulonglong2). Double-buffered gather; 1 barrier / 8 edges.
// Cross-k reduce = shfl_xor(16); scatter = predicated scalar red.
// ---------------------------------------------------------------------------
#define EPB 8

__global__ __launch_bounds__(128, 4)
void k_edge2(const int* __restrict__ ei,
             const float* __restrict__ ea,
             const float* __restrict__ A2,
             const float* __restrict__ b2,
             float* __restrict__ out,
             int E, int N)
{
    const int tid  = threadIdx.x;
    const int warp = tid >> 5;
    const int lane = tid & 31;
    const int col  = warp * 16 + (lane & 15);
    const int g    = lane >> 4;       // k half
    const int kbase = g * 32;

    // Weight cache: 16 packed k-pairs for this (col, g) slice.
    unsigned long long A0p[16], A1p[16], Bp[16];
#pragma unroll
    for (int kk = 0; kk < 16; kk++) {
        int k0 = kbase + 2 * kk;
        A0p[kk] = pk2(__ldg(&A2[k0 * 64 + col]),        __ldg(&A2[(k0 + 1) * 64 + col]));
        A1p[kk] = pk2(__ldg(&A2[4096 + k0 * 64 + col]), __ldg(&A2[4096 + (k0 + 1) * 64 + col]));
        Bp[kk]  = pk2(__ldg(&b2[k0 * 64 + col]),        __ldg(&b2[(k0 + 1) * 64 + col]));
    }

    __shared__ __align__(16) float hs[2][EPB][64];
    __shared__ float2 sAm[2][EPB];
    __shared__ int    sDst[2][EPB];

    const int nbatch = (E + EPB - 1) / EPB;
    const int gj = tid >> 4;   // 0..7: edge row for gather
    const int gq = tid & 15;   // float4 quad within row

    auto load_batch = [&](int b, int buf) {
        int e = b * EPB + gj;
        int src = 0;
        if (e < E) src = clamp_idx(__ldg(&ei[e]), N);
        reinterpret_cast<float4*>(&hs[buf][gj][0])[gq] =
            reinterpret_cast<const float4*>(g_h + (size_t)src * 64)[gq];
        if (tid < EPB) {
            int em = b * EPB + tid;
            float2 a = make_float2(0.0f, 0.0f);
            int dst = 0;
            if (em < E) {
                a = __ldg(reinterpret_cast<const float2*>(ea) + em);
                dst = clamp_idx(__ldg(&ei[E + em]), N);
            }
            sAm[buf][tid] = a;
            sDst[buf][tid] = dst;
        }
    };

    int b = blockIdx.x;
    int buf = 0;
    if (b < nbatch) load_batch(b, 0);
    __syncthreads();

    while (b < nbatch) {
        int bn = b + gridDim.x;
        if (bn < nbatch) load_batch(bn, buf ^ 1);

        int e0 = b * EPB;
#pragma unroll 2
        for (int j = 0; j < EPB; j++) {
            float2 a = sAm[buf][j];
            unsigned long long a0p = pk2(a.x, a.x);
            unsigned long long a1p = pk2(a.y, a.y);
            const ulonglong2* hp =
                reinterpret_cast<const ulonglong2*>(&hs[buf][j][kbase]);

            unsigned long long acc2 = 0ull;
#pragma unroll
            for (int t = 0; t < 8; t++) {
                ulonglong2 hv = hp[t];  // 2 packed k-pairs via LDS.128
                unsigned long long w0 =
                    ffma2(a1p, A1p[2 * t], ffma2(a0p, A0p[2 * t], Bp[2 * t]));
                acc2 = ffma2(relu2(w0), hv.x, acc2);
                unsigned long long w1 =
                    ffma2(a1p, A1p[2 * t + 1], ffma2(a0p, A0p[2 * t + 1], Bp[2 * t + 1]));
                acc2 = ffma2(relu2(w1), hv.y, acc2);
            }
            float al, ah;
            upk2(acc2, al, ah);
            float acc = al + ah;
            acc += __shfl_xor_sync(0xffffffffu, acc, 16);  // combine k halves
            if (g == 0 && (e0 + j) < E) {
                float* p = out + (size_t)sDst[buf][j] * 64 + col;
                asm volatile("red.global.add.f32 [%0], %1;"
                             :: "l"(p), "f"(acc) : "memory");
            }
        }
        __syncthreads();
        buf ^= 1;
        b = bn;
    }
}

// ---------------------------------------------------------------------------
// Launch
// ---------------------------------------------------------------------------
extern "C" void kernel_launch(void* const* d_in, const int* in_sizes, int n_in,
                              void* d_out, int out_size)
{
    const float* x     = (const float*)d_in[0];
    const int*   ei    = (const int*)d_in[1];
    const float* ea    = (const float*)d_in[2];
    const float* A1    = (const float*)d_in[3];
    const float* b1    = (const float*)d_in[4];
    const float* A2    = (const float*)d_in[5];
    const float* b2    = (const float*)d_in[6];
    const float* root1 = (const float*)d_in[7];
    const float* bias1 = (const float*)d_in[8];
    const float* root2 = (const float*)d_in[9];
    const float* bias2 = (const float*)d_in[10];
    float* out = (float*)d_out;

    const int N = in_sizes[0] / C1_IN;   // 16384
    const int E = in_sizes[1] / 2;       // 65536

    {
        int total = N * 64;
        int blocks = (total + 255) / 256;
        k_node1<<<blocks, 256>>>(x, root1, bias1, N);
    }
    k_edge1<<<592, 256>>>(x, ei, ea, A1, b1, E, N);
    k_node2<<<512, 256>>>(root2, bias2, out, N);
    k_edge2<<<592, 128>>>(ei, ea, A2, b2, out, E, N);
}

// round 11
// speedup vs baseline: 1.4776x; 1.4034x over previous
#include <cuda_runtime.h>
#include <cuda_fp16.h>
#include <cstdint>

#define C1_IN 8
#define NN 16384
#define EPB 16

__device__ float g_h[NN * 64];

__device__ __forceinline__ int clamp_idx(int v, int n) {
    v = v < 0 ? 0 : v;
    return v >= n ? n - 1 : v;
}
__device__ __forceinline__ unsigned long long pk2(float lo, float hi) {
    unsigned long long r;
    asm("mov.b64 %0, {%1, %2};" : "=l"(r) : "f"(lo), "f"(hi));
    return r;
}
__device__ __forceinline__ void upk2(unsigned long long v, float& lo, float& hi) {
    asm("mov.b64 {%0, %1}, %2;" : "=f"(lo), "=f"(hi) : "l"(v));
}
__device__ __forceinline__ unsigned long long ffma2(unsigned long long a,
                                                    unsigned long long b,
                                                    unsigned long long c) {
    unsigned long long d;
    asm("fma.rn.f32x2 %0, %1, %2, %3;" : "=l"(d) : "l"(a), "l"(b), "l"(c));
    return d;
}
__device__ __forceinline__ unsigned long long relu2(unsigned long long v) {
    float lo, hi;
    upk2(v, lo, hi);
    return pk2(fmaxf(lo, 0.0f), fmaxf(hi, 0.0f));
}

// ---------------------------------------------------------------------------
// Kernel A: fused layer-1.  Blocks [0, GA_EDGE) = edge1 role (fp32 packed),
// blocks [GA_EDGE, grid) = node1 role (root term).  Both red.add into g_h,
// which is zeroed by cudaMemsetAsync beforehand.
// ---------------------------------------------------------------------------
__global__ __launch_bounds__(256)
void k_A(const float* __restrict__ x,
         const int* __restrict__ ei,
         const float* __restrict__ ea,
         const float* __restrict__ A1,
         const float* __restrict__ b1,
         const float* __restrict__ root1,
         const float* __restrict__ bias1,
         int E, int N, int GA_EDGE)
{
    if (blockIdx.x < GA_EDGE) {
        // ---- edge1 role: warp-autonomous, lane owns cols (2l, 2l+1) ----
        const int lane = threadIdx.x & 31;
        const int c0 = 2 * lane;

        unsigned long long A0p[8], A1p[8], Bp[8];
#pragma unroll
        for (int k = 0; k < 8; k++) {
            A0p[k] = pk2(__ldg(&A1[k * 64 + c0]),       __ldg(&A1[k * 64 + c0 + 1]));
            A1p[k] = pk2(__ldg(&A1[512 + k * 64 + c0]), __ldg(&A1[512 + k * 64 + c0 + 1]));
            Bp[k]  = pk2(__ldg(&b1[k * 64 + c0]),       __ldg(&b1[k * 64 + c0 + 1]));
        }

        const int gw = (blockIdx.x * blockDim.x + threadIdx.x) >> 5;
        const int nw = (GA_EDGE * blockDim.x) >> 5;

        for (int e0 = gw * 2; e0 < E; e0 += nw * 2) {
#pragma unroll
            for (int u = 0; u < 2; u++) {
                int e = e0 + u;
                if (e >= E) break;
                int src = clamp_idx(__ldg(&ei[e]), N);
                int dst = clamp_idx(__ldg(&ei[E + e]), N);
                float2 a = __ldg(reinterpret_cast<const float2*>(ea) + e);
                unsigned long long a0p = pk2(a.x, a.x);
                unsigned long long a1p = pk2(a.y, a.y);

                float xv = (lane < C1_IN) ? __ldg(&x[src * C1_IN + lane]) : 0.0f;

                unsigned long long acc2 = 0ull;
#pragma unroll
                for (int k = 0; k < 8; k++) {
                    float xk = __shfl_sync(0xffffffffu, xv, k);
                    unsigned long long w = ffma2(a1p, A1p[k], ffma2(a0p, A0p[k], Bp[k]));
                    acc2 = ffma2(relu2(w), pk2(xk, xk), acc2);
                }
                float acc0, acc1;
                upk2(acc2, acc0, acc1);
                float* p = g_h + (size_t)dst * 64 + c0;
                asm volatile("red.global.add.v2.f32 [%0], {%1, %2};"
                             :: "l"(p), "f"(acc0), "f"(acc1) : "memory");
            }
        }
    } else {
        // ---- node1 role: g_h[n, 2op..2op+1] += bias1 + x[n,:] @ root1 ----
        int nblk = gridDim.x - GA_EDGE;
        int id = (blockIdx.x - GA_EDGE) * blockDim.x + threadIdx.x;
        int stride = nblk * blockDim.x;
        for (int p = id; p < N * 32; p += stride) {
            int n = p >> 5, op = p & 31;
            const float* xr = x + n * C1_IN;
            float acc0 = __ldg(&bias1[2 * op]);
            float acc1 = __ldg(&bias1[2 * op + 1]);
#pragma unroll
            for (int i = 0; i < C1_IN; i++) {
                float xv = __ldg(&xr[i]);
                acc0 = fmaf(xv, __ldg(&root1[i * 64 + 2 * op]), acc0);
                acc1 = fmaf(xv, __ldg(&root1[i * 64 + 2 * op + 1]), acc1);
            }
            float* pp = g_h + (size_t)n * 64 + 2 * op;
            asm volatile("red.global.add.v2.f32 [%0], {%1, %2};"
                         :: "l"(pp), "f"(acc0), "f"(acc1) : "memory");
        }
    }
}

// ---------------------------------------------------------------------------
// Kernel B: fused layer-2.  Blocks [0, GB_EDGE) = edge2 role (fp16x2 with
// fused-relu HFMA2), blocks [GB_EDGE, grid) = node2 role (fp32 root term).
// Both red.add into out, zeroed by cudaMemsetAsync beforehand.
// ---------------------------------------------------------------------------
__global__ __launch_bounds__(128, 5)
void k_B(const int* __restrict__ ei,
         const float* __restrict__ ea,
         const float* __restrict__ A2,
         const float* __restrict__ b2,
         const float* __restrict__ root2,
         const float* __restrict__ bias2,
         float* __restrict__ out,
         int E, int N, int GB_EDGE)
{
    // Static smem for both roles (sums; 128-thread blocks).
    __shared__ __align__(16) __half2 hs[2][EPB][32];
    __shared__ __half2 sA0[2][EPB], sA1[2][EPB];
    __shared__ int     sDst[2][EPB];
    __shared__ __align__(16) float r2[4096];

    const int tid = threadIdx.x;

    if (blockIdx.x < GB_EDGE) {
        // ---- edge2 role ----
        const int warp = tid >> 5;
        const int lane = tid & 31;
        const int col  = warp * 16 + (lane & 15);
        const int g    = lane >> 4;      // k half: [g*32, g*32+32)
        const int kbase = g * 32;

        // fp16x2 weight cache: 16 k-pairs for this (col, g): 48 regs.
        __half2 A0h[16], A1h[16], Bh[16];
#pragma unroll
        for (int kk = 0; kk < 16; kk++) {
            int k0 = kbase + 2 * kk;
            A0h[kk] = __floats2half2_rn(__ldg(&A2[k0 * 64 + col]),
                                        __ldg(&A2[(k0 + 1) * 64 + col]));
            A1h[kk] = __floats2half2_rn(__ldg(&A2[4096 + k0 * 64 + col]),
                                        __ldg(&A2[4096 + (k0 + 1) * 64 + col]));
            Bh[kk]  = __floats2half2_rn(__ldg(&b2[k0 * 64 + col]),
                                        __ldg(&b2[(k0 + 1) * 64 + col]));
        }

        const int nbatch = (E + EPB - 1) / EPB;

        auto load_batch = [&](int b, int buf) {
            // 16 rows x 16 float4-quads = 256 slots, 128 threads x 2.
#pragma unroll
            for (int r = 0; r < 2; r++) {
                int idx = tid + r * 128;
                int row = idx >> 4, q = idx & 15;
                int e = b * EPB + row;
                int src = 0;
                if (e < E) src = clamp_idx(__ldg(&ei[e]), N);
                float4 v = *reinterpret_cast<const float4*>(
                    g_h + (size_t)src * 64 + q * 4);
                hs[buf][row][q * 2]     = __floats2half2_rn(v.x, v.y);
                hs[buf][row][q * 2 + 1] = __floats2half2_rn(v.z, v.w);
            }
            if (tid < EPB) {
                int em = b * EPB + tid;
                float2 a = make_float2(0.0f, 0.0f);
                int dst = 0;
                if (em < E) {
                    a = __ldg(reinterpret_cast<const float2*>(ea) + em);
                    dst = clamp_idx(__ldg(&ei[E + em]), N);
                }
                sA0[buf][tid] = __float2half2_rn(a.x);
                sA1[buf][tid] = __float2half2_rn(a.y);
                sDst[buf][tid] = dst;
            }
        };

        int b = blockIdx.x;
        int buf = 0;
        if (b < nbatch) load_batch(b, 0);
        __syncthreads();

        while (b < nbatch) {
            int bn = b + GB_EDGE;
            if (bn < nbatch) load_batch(bn, buf ^ 1);

            int e0 = b * EPB;
#pragma unroll 2
            for (int j = 0; j < EPB; j++) {
                __half2 a0 = sA0[buf][j];
                __half2 a1 = sA1[buf][j];
                const uint4* hp =
                    reinterpret_cast<const uint4*>(&hs[buf][j][g * 16]);

                __half2 acca = __float2half2_rn(0.0f);
                __half2 accb = __float2half2_rn(0.0f);
#pragma unroll
                for (int t = 0; t < 4; t++) {
                    uint4 hv = hp[t];  // 4 half2 = 4 k-pairs (LDS.128 broadcast)
                    __half2 h0 = *reinterpret_cast<const __half2*>(&hv.x);
                    __half2 h1 = *reinterpret_cast<const __half2*>(&hv.y);
                    __half2 h2 = *reinterpret_cast<const __half2*>(&hv.z);
                    __half2 h3 = *reinterpret_cast<const __half2*>(&hv.w);
                    __half2 w;
                    w = __hfma2(a0, A0h[4 * t + 0], Bh[4 * t + 0]);
                    w = __hfma2_relu(a1, A1h[4 * t + 0], w);
                    acca = __hfma2(w, h0, acca);
                    w = __hfma2(a0, A0h[4 * t + 1], Bh[4 * t + 1]);
                    w = __hfma2_relu(a1, A1h[4 * t + 1], w);
                    accb = __hfma2(w, h1, accb);
                    w = __hfma2(a0, A0h[4 * t + 2], Bh[4 * t + 2]);
                    w = __hfma2_relu(a1, A1h[4 * t + 2], w);
                    acca = __hfma2(w, h2, acca);
                    w = __hfma2(a0, A0h[4 * t + 3], Bh[4 * t + 3]);
                    w = __hfma2_relu(a1, A1h[4 * t + 3], w);
                    accb = __hfma2(w, h3, accb);
                }
                float2 f0 = __half22float2(acca);
                float2 f1 = __half22float2(accb);
                float acc = (f0.x + f0.y) + (f1.x + f1.y);
                acc += __shfl_xor_sync(0xffffffffu, acc, 16);  // combine k halves
                if (g == 0 && (e0 + j) < E) {
                    float* p = out + (size_t)sDst[buf][j] * 64 + col;
                    asm volatile("red.global.add.f32 [%0], %1;"
                                 :: "l"(p), "f"(acc) : "memory");
                }
            }
            __syncthreads();
            buf ^= 1;
            b = bn;
        }
    } else {
        // ---- node2 role: out[n, 2op..2op+1] += bias2 + h[n,:] @ root2 ----
        for (int i = tid; i < 4096; i += 128)
            r2[i] = __ldg(&root2[i]);
        __syncthreads();

        const int op = tid & 31;   // col pair
        const int j  = tid >> 5;   // 0..3
        float2 bv = __ldg(reinterpret_cast<const float2*>(bias2) + op);
        const unsigned long long bp = pk2(bv.x, bv.y);
        const unsigned long long* r2p =
            reinterpret_cast<const unsigned long long*>(r2);

        int nblk = gridDim.x - GB_EDGE;
        for (int nb = (blockIdx.x - GB_EDGE) * 4; nb < N; nb += nblk * 4) {
            int n = nb + j;
            const float4* hr = reinterpret_cast<const float4*>(g_h + (size_t)n * 64);
            unsigned long long acc = bp;
#pragma unroll
            for (int q = 0; q < 16; q++) {
                float4 hv = hr[q];
                acc = ffma2(pk2(hv.x, hv.x), r2p[(q * 4 + 0) * 32 + op], acc);
                acc = ffma2(pk2(hv.y, hv.y), r2p[(q * 4 + 1) * 32 + op], acc);
                acc = ffma2(pk2(hv.z, hv.z), r2p[(q * 4 + 2) * 32 + op], acc);
                acc = ffma2(pk2(hv.w, hv.w), r2p[(q * 4 + 3) * 32 + op], acc);
            }
            float ol, oh;
            upk2(acc, ol, oh);
            float* po = out + (size_t)n * 64 + 2 * op;
            asm volatile("red.global.add.v2.f32 [%0], {%1, %2};"
                         :: "l"(po), "f"(ol), "f"(oh) : "memory");
        }
    }
}

// ---------------------------------------------------------------------------
// Launch: memset g_h + out, then 2 fused kernels.
// ---------------------------------------------------------------------------
extern "C" void kernel_launch(void* const* d_in, const int* in_sizes, int n_in,
                              void* d_out, int out_size)
{
    const float* x     = (const float*)d_in[0];
    const int*   ei    = (const int*)d_in[1];
    const float* ea    = (const float*)d_in[2];
    const float* A1    = (const float*)d_in[3];
    const float* b1    = (const float*)d_in[4];
    const float* A2    = (const float*)d_in[5];
    const float* b2    = (const float*)d_in[6];
    const float* root1 = (const float*)d_in[7];
    const float* bias1 = (const float*)d_in[8];
    const float* root2 = (const float*)d_in[9];
    const float* bias2 = (const float*)d_in[10];
    float* out = (float*)d_out;

    const int N = in_sizes[0] / C1_IN;   // 16384
    const int E = in_sizes[1] / 2;       // 65536

    void* hptr = nullptr;
    cudaGetSymbolAddress(&hptr, g_h);
    cudaMemsetAsync(hptr, 0, (size_t)NN * 64 * sizeof(float));
    cudaMemsetAsync(out, 0, (size_t)out_size * sizeof(float));

    const int GA_EDGE = 592;
    k_A<<<GA_EDGE + 296, 256>>>(x, ei, ea, A1, b1, root1, bias1, E, N, GA_EDGE);

    const int GB_EDGE = 740;
    k_B<<<GB_EDGE + 296, 128>>>(ei, ea, A2, b2, root2, bias2, out, E, N, GB_EDGE);
}

// round 15
// speedup vs baseline: 1.5365x; 1.0399x over previous
#include <cuda_runtime.h>
#include <cuda_fp16.h>
#include <cstdint>

#define C1_IN 8
#define NN 16384
#define EPB 16

// h stored as fp16 pairs: g_h16[n*32 + c/2] holds cols (2c, 2c+1).
__device__ __half2 g_h16[NN * 32];

__device__ __forceinline__ int clamp_idx(int v, int n) {
    v = v < 0 ? 0 : v;
    return v >= n ? n - 1 : v;
}
__device__ __forceinline__ unsigned long long pk2(float lo, float hi) {
    unsigned long long r;
    asm("mov.b64 %0, {%1, %2};" : "=l"(r) : "f"(lo), "f"(hi));
    return r;
}
__device__ __forceinline__ void upk2(unsigned long long v, float& lo, float& hi) {
    asm("mov.b64 {%0, %1}, %2;" : "=f"(lo), "=f"(hi) : "l"(v));
}
__device__ __forceinline__ unsigned long long ffma2(unsigned long long a,
                                                    unsigned long long b,
                                                    unsigned long long c) {
    unsigned long long d;
    asm("fma.rn.f32x2 %0, %1, %2, %3;" : "=l"(d) : "l"(a), "l"(b), "l"(c));
    return d;
}
__device__ __forceinline__ unsigned long long relu2(unsigned long long v) {
    float lo, hi;
    upk2(v, lo, hi);
    return pk2(fmaxf(lo, 0.0f), fmaxf(hi, 0.0f));
}
__device__ __forceinline__ void red_f16x2(__half2* p, float lo, float hi) {
    __half2 v = __floats2half2_rn(lo, hi);
    unsigned int uv = *reinterpret_cast<unsigned int*>(&v);
    asm volatile("red.global.add.noftz.f16x2 [%0], %1;"
                 :: "l"(p), "r"(uv) : "memory");
}
__device__ __forceinline__ __half2 h2_of(unsigned int u) {
    return *reinterpret_cast<__half2*>(&u);
}

// ---------------------------------------------------------------------------
// Kernel A: fused layer-1 -> g_h16 (zeroed beforehand).
// Blocks [0, GA_EDGE) = edge1 (fp32 math, f16x2 red scatter);
// rest = node1 root term.
// ---------------------------------------------------------------------------
__global__ __launch_bounds__(256)
void k_A(const float* __restrict__ x,
         const int* __restrict__ ei,
         const float* __restrict__ ea,
         const float* __restrict__ A1,
         const float* __restrict__ b1,
         const float* __restrict__ root1,
         const float* __restrict__ bias1,
         int E, int N, int GA_EDGE)
{
    if (blockIdx.x < GA_EDGE) {
        const int lane = threadIdx.x & 31;
        const int c0 = 2 * lane;

        unsigned long long A0p[8], A1p[8], Bp[8];
#pragma unroll
        for (int k = 0; k < 8; k++) {
            A0p[k] = pk2(__ldg(&A1[k * 64 + c0]),       __ldg(&A1[k * 64 + c0 + 1]));
            A1p[k] = pk2(__ldg(&A1[512 + k * 64 + c0]), __ldg(&A1[512 + k * 64 + c0 + 1]));
            Bp[k]  = pk2(__ldg(&b1[k * 64 + c0]),       __ldg(&b1[k * 64 + c0 + 1]));
        }

        const int gw = (blockIdx.x * blockDim.x + threadIdx.x) >> 5;
        const int nw = (GA_EDGE * blockDim.x) >> 5;

        for (int e0 = gw * 2; e0 < E; e0 += nw * 2) {
#pragma unroll
            for (int u = 0; u < 2; u++) {
                int e = e0 + u;
                if (e >= E) break;
                int src = clamp_idx(__ldg(&ei[e]), N);
                int dst = clamp_idx(__ldg(&ei[E + e]), N);
                float2 a = __ldg(reinterpret_cast<const float2*>(ea) + e);
                unsigned long long a0p = pk2(a.x, a.x);
                unsigned long long a1p = pk2(a.y, a.y);

                float xv = (lane < C1_IN) ? __ldg(&x[src * C1_IN + lane]) : 0.0f;

                unsigned long long acc2 = 0ull;
#pragma unroll
                for (int k = 0; k < 8; k++) {
                    float xk = __shfl_sync(0xffffffffu, xv, k);
                    unsigned long long w = ffma2(a1p, A1p[k], ffma2(a0p, A0p[k], Bp[k]));
                    acc2 = ffma2(relu2(w), pk2(xk, xk), acc2);
                }
                float acc0, acc1;
                upk2(acc2, acc0, acc1);
                red_f16x2(g_h16 + (size_t)dst * 32 + lane, acc0, acc1);
            }
        }
    } else {
        // node1 role: g_h16[n, op] += (bias1 + x[n,:] @ root1) cols (2op,2op+1)
        int nblk = gridDim.x - GA_EDGE;
        int id = (blockIdx.x - GA_EDGE) * blockDim.x + threadIdx.x;
        int stride = nblk * blockDim.x;
        for (int p = id; p < N * 32; p += stride) {
            int n = p >> 5, op = p & 31;
            const float* xr = x + n * C1_IN;
            float acc0 = __ldg(&bias1[2 * op]);
            float acc1 = __ldg(&bias1[2 * op + 1]);
#pragma unroll
            for (int i = 0; i < C1_IN; i++) {
                float xv = __ldg(&xr[i]);
                acc0 = fmaf(xv, __ldg(&root1[i * 64 + 2 * op]), acc0);
                acc1 = fmaf(xv, __ldg(&root1[i * 64 + 2 * op + 1]), acc1);
            }
            red_f16x2(g_h16 + (size_t)n * 32 + op, acc0, acc1);
        }
    }
}

// ---------------------------------------------------------------------------
// Kernel B: fused layer-2 -> out (zeroed beforehand).
// Blocks [0, GB_EDGE): edge2, fp16x2 HFMA2 with fused relu, 2-edge interleave.
// Rest: node2 root term (fp32, reads g_h16).
// ---------------------------------------------------------------------------
__global__ __launch_bounds__(128, 4)
void k_B(const int* __restrict__ ei,
         const float* __restrict__ ea,
         const float* __restrict__ A2,
         const float* __restrict__ b2,
         const float* __restrict__ root2,
         const float* __restrict__ bias2,
         float* __restrict__ out,
         int E, int N, int GB_EDGE)
{
    __shared__ __align__(16) __half2 hs[2][EPB][32];
    __shared__ __half2 sA0[2][EPB], sA1[2][EPB];
    __shared__ int     sDst[2][EPB];
    __shared__ __align__(16) float r2[4096];

    const int tid = threadIdx.x;

    if (blockIdx.x < GB_EDGE) {
        const int warp = tid >> 5;
        const int lane = tid & 31;
        const int col  = warp * 16 + (lane & 15);
        const int g    = lane >> 4;      // k half: [g*32, g*32+32)
        const int kbase = g * 32;

        // fp16x2 weight cache: 16 k-pairs for this (col, g): 48 regs.
        __half2 A0h[16], A1h[16], Bh[16];
#pragma unroll
        for (int kk = 0; kk < 16; kk++) {
            int k0 = kbase + 2 * kk;
            A0h[kk] = __floats2half2_rn(__ldg(&A2[k0 * 64 + col]),
                                        __ldg(&A2[(k0 + 1) * 64 + col]));
            A1h[kk] = __floats2half2_rn(__ldg(&A2[4096 + k0 * 64 + col]),
                                        __ldg(&A2[4096 + (k0 + 1) * 64 + col]));
            Bh[kk]  = __floats2half2_rn(__ldg(&b2[k0 * 64 + col]),
                                        __ldg(&b2[(k0 + 1) * 64 + col]));
        }

        const int nbatch = (E + EPB - 1) / EPB;

        // 16 rows x 8 uint4 (row = 32 half2 = 128B) = 128 uint4; one per thread.
        auto load_batch = [&](int b, int buf) {
            int row = tid >> 3, q = tid & 7;
            int e = b * EPB + row;
            int src = 0;
            if (e < E) src = clamp_idx(__ldg(&ei[e]), N);
            uint4 v = *reinterpret_cast<const uint4*>(
                g_h16 + (size_t)src * 32 + q * 4);
            *reinterpret_cast<uint4*>(&hs[buf][row][q * 4]) = v;
            if (tid < EPB) {
                int em = b * EPB + tid;
                float2 a = make_float2(0.0f, 0.0f);
                int dst = 0;
                if (em < E) {
                    a = __ldg(reinterpret_cast<const float2*>(ea) + em);
                    dst = clamp_idx(__ldg(&ei[E + em]), N);
                }
                sA0[buf][tid] = __float2half2_rn(a.x);
                sA1[buf][tid] = __float2half2_rn(a.y);
                sDst[buf][tid] = dst;
            }
        };

        int b = blockIdx.x;
        int buf = 0;
        if (b < nbatch) load_batch(b, 0);
        __syncthreads();

        while (b < nbatch) {
            int bn = b + GB_EDGE;
            if (bn < nbatch) load_batch(bn, buf ^ 1);

            int e0 = b * EPB;
#pragma unroll 2
            for (int j = 0; j < EPB; j += 2) {
                __half2 a0A = sA0[buf][j],     a1A = sA1[buf][j];
                __half2 a0B = sA0[buf][j + 1], a1B = sA1[buf][j + 1];
                const uint4* hpA = reinterpret_cast<const uint4*>(&hs[buf][j][g * 16]);
                const uint4* hpB = reinterpret_cast<const uint4*>(&hs[buf][j + 1][g * 16]);

                __half2 zero = __float2half2_rn(0.0f);
                __half2 accA0 = zero, accA1 = zero, accB0 = zero, accB1 = zero;
#pragma unroll
                for (int t = 0; t < 4; t++) {
                    uint4 hA = hpA[t];   // 4 half2 = 4 k-pairs (LDS.128)
                    uint4 hB = hpB[t];
                    __half2 w;
                    w = __hfma2(a0A, A0h[4 * t + 0], Bh[4 * t + 0]);
                    w = __hfma2_relu(a1A, A1h[4 * t + 0], w);
                    accA0 = __hfma2(w, h2_of(hA.x), accA0);
                    w = __hfma2(a0B, A0h[4 * t + 0], Bh[4 * t + 0]);
                    w = __hfma2_relu(a1B, A1h[4 * t + 0], w);
                    accB0 = __hfma2(w, h2_of(hB.x), accB0);

                    w = __hfma2(a0A, A0h[4 * t + 1], Bh[4 * t + 1]);
                    w = __hfma2_relu(a1A, A1h[4 * t + 1], w);
                    accA1 = __hfma2(w, h2_of(hA.y), accA1);
                    w = __hfma2(a0B, A0h[4 * t + 1], Bh[4 * t + 1]);
                    w = __hfma2_relu(a1B, A1h[4 * t + 1], w);
                    accB1 = __hfma2(w, h2_of(hB.y), accB1);

                    w = __hfma2(a0A, A0h[4 * t + 2], Bh[4 * t + 2]);
                    w = __hfma2_relu(a1A, A1h[4 * t + 2], w);
                    accA0 = __hfma2(w, h2_of(hA.z), accA0);
                    w = __hfma2(a0B, A0h[4 * t + 2], Bh[4 * t + 2]);
                    w = __hfma2_relu(a1B, A1h[4 * t + 2], w);
                    accB0 = __hfma2(w, h2_of(hB.z), accB0);

                    w = __hfma2(a0A, A0h[4 * t + 3], Bh[4 * t + 3]);
                    w = __hfma2_relu(a1A, A1h[4 * t + 3], w);
                    accA1 = __hfma2(w, h2_of(hA.w), accA1);
                    w = __hfma2(a0B, A0h[4 * t + 3], Bh[4 * t + 3]);
                    w = __hfma2_relu(a1B, A1h[4 * t + 3], w);
                    accB1 = __hfma2(w, h2_of(hB.w), accB1);
                }
                // Epilogues for both edges.
                {
                    __half2 s = __hadd2(accA0, accA1);
                    float2 f = __half22float2(s);
                    float acc = f.x + f.y;
                    acc += __shfl_xor_sync(0xffffffffu, acc, 16);
                    if (g == 0 && (e0 + j) < E) {
                        float* p = out + (size_t)sDst[buf][j] * 64 + col;
                        asm volatile("red.global.add.f32 [%0], %1;"
                                     :: "l"(p), "f"(acc) : "memory");
                    }
                }
                {
                    __half2 s = __hadd2(accB0, accB1);
                    float2 f = __half22float2(s);
                    float acc = f.x + f.y;
                    acc += __shfl_xor_sync(0xffffffffu, acc, 16);
                    if (g == 0 && (e0 + j + 1) < E) {
                        float* p = out + (size_t)sDst[buf][j + 1] * 64 + col;
                        asm volatile("red.global.add.f32 [%0], %1;"
                                     :: "l"(p), "f"(acc) : "memory");
                    }
                }
            }
            __syncthreads();
            buf ^= 1;
            b = bn;
        }
    } else {
        // node2 role: out[n, 2op..2op+1] += bias2 + h[n,:] @ root2 (fp32 math)
        for (int i = tid; i < 4096; i += 128)
            r2[i] = __ldg(&root2[i]);
        __syncthreads();

        const int op = tid & 31;
        const int j  = tid >> 5;   // 0..3
        float2 bv = __ldg(reinterpret_cast<const float2*>(bias2) + op);
        const unsigned long long bp = pk2(bv.x, bv.y);
        const unsigned long long* r2p =
            reinterpret_cast<const unsigned long long*>(r2);

        int nblk = gridDim.x - GB_EDGE;
        for (int nb = (blockIdx.x - GB_EDGE) * 4; nb < N; nb += nblk * 4) {
            int n = nb + j;
            // Full row: 32 half2 = 8 uint4 = 64 cols (k values).
            const uint4* hr = reinterpret_cast<const uint4*>(g_h16 + (size_t)n * 32);
            unsigned int hw[32];
#pragma unroll
            for (int t = 0; t < 8; t++)
                *reinterpret_cast<uint4*>(&hw[4 * t]) = hr[t];

            unsigned long long acc = bp;
#pragma unroll
            for (int q = 0; q < 32; q++) {
                float2 f = __half22float2(h2_of(hw[q]));
                acc = ffma2(pk2(f.x, f.x), r2p[(2 * q) * 32 + op], acc);
                acc = ffma2(pk2(f.y, f.y), r2p[(2 * q + 1) * 32 + op], acc);
            }
            float ol, oh;
            upk2(acc, ol, oh);
            float* po = out + (size_t)n * 64 + 2 * op;
            asm volatile("red.global.add.v2.f32 [%0], {%1, %2};"
                         :: "l"(po), "f"(ol), "f"(oh) : "memory");
        }
    }
}

// ---------------------------------------------------------------------------
// Launch
// ---------------------------------------------------------------------------
extern "C" void kernel_launch(void* const* d_in, const int* in_sizes, int n_in,
                              void* d_out, int out_size)
{
    const float* x     = (const float*)d_in[0];
    const int*   ei    = (const int*)d_in[1];
    const float* ea    = (const float*)d_in[2];
    const float* A1    = (const float*)d_in[3];
    const float* b1    = (const float*)d_in[4];
    const float* A2    = (const float*)d_in[5];
    const float* b2    = (const float*)d_in[6];
    const float* root1 = (const float*)d_in[7];
    const float* bias1 = (const float*)d_in[8];
    const float* root2 = (const float*)d_in[9];
    const float* bias2 = (const float*)d_in[10];
    float* out = (float*)d_out;

    const int N = in_sizes[0] / C1_IN;   // 16384
    const int E = in_sizes[1] / 2;       // 65536

    void* hptr = nullptr;
    cudaGetSymbolAddress(&hptr, g_h16);
    cudaMemsetAsync(hptr, 0, (size_t)NN * 32 * sizeof(__half2));
    cudaMemsetAsync(out, 0, (size_t)out_size * sizeof(float));

    const int GA_EDGE = 592;
    k_A<<<GA_EDGE + 296, 256>>>(x, ei, ea, A1, b1, root1, bias1, E, N, GA_EDGE);

    const int GB_EDGE = 740;
    k_B<<<GB_EDGE + 296, 128>>>(ei, ea, A2, b2, root2, bias2, out, E, N, GB_EDGE);
}

// round 16
// speedup vs baseline: 1.7013x; 1.1072x over previous
#include <cuda_runtime.h>
#include <cuda_fp16.h>
#include <cstdint>

#define C1_IN 8
#define NN 16384
#define EPB 16

// h stored as fp16 pairs: g_h16[n*32 + c/2] holds cols (2c, 2c+1).
__device__ __half2 g_h16[NN * 32];

__device__ __forceinline__ int clamp_idx(int v, int n) {
    v = v < 0 ? 0 : v;
    return v >= n ? n - 1 : v;
}
__device__ __forceinline__ unsigned long long pk2(float lo, float hi) {
    unsigned long long r;
    asm("mov.b64 %0, {%1, %2};" : "=l"(r) : "f"(lo), "f"(hi));
    return r;
}
__device__ __forceinline__ void upk2(unsigned long long v, float& lo, float& hi) {
    asm("mov.b64 {%0, %1}, %2;" : "=f"(lo), "=f"(hi) : "l"(v));
}
__device__ __forceinline__ unsigned long long ffma2(unsigned long long a,
                                                    unsigned long long b,
                                                    unsigned long long c) {
    unsigned long long d;
    asm("fma.rn.f32x2 %0, %1, %2, %3;" : "=l"(d) : "l"(a), "l"(b), "l"(c));
    return d;
}
__device__ __forceinline__ void red_f16x2(__half2* p, float lo, float hi) {
    __half2 v = __floats2half2_rn(lo, hi);
    unsigned int uv = *reinterpret_cast<unsigned int*>(&v);
    asm volatile("red.global.add.noftz.f16x2 [%0], %1;"
                 :: "l"(p), "r"(uv) : "memory");
}
__device__ __forceinline__ void red_h2(__half2* p, __half2 v) {
    unsigned int uv = *reinterpret_cast<unsigned int*>(&v);
    asm volatile("red.global.add.noftz.f16x2 [%0], %1;"
                 :: "l"(p), "r"(uv) : "memory");
}
__device__ __forceinline__ __half2 h2_of(unsigned int u) {
    return *reinterpret_cast<__half2*>(&u);
}
__device__ __forceinline__ unsigned int u_of(__half2 h) {
    return *reinterpret_cast<unsigned int*>(&h);
}

// ---------------------------------------------------------------------------
// Kernel A: fused layer-1 -> g_h16 (zeroed beforehand).
// Blocks [0, GA_EDGE) = edge1 in fp16 (HFMA2, fused relu, half2 over col-pair);
// rest = node1 root term (fp32).
// ---------------------------------------------------------------------------
__global__ __launch_bounds__(256)
void k_A(const float* __restrict__ x,
         const int* __restrict__ ei,
         const float* __restrict__ ea,
         const float* __restrict__ A1,
         const float* __restrict__ b1,
         const float* __restrict__ root1,
         const float* __restrict__ bias1,
         int E, int N, int GA_EDGE)
{
    if (blockIdx.x < GA_EDGE) {
        const int lane = threadIdx.x & 31;
        const int c0 = 2 * lane;

        // fp16 weight cache packed over the col-pair: 24 regs.
        __half2 A0h[8], A1h[8], Bh[8];
#pragma unroll
        for (int k = 0; k < 8; k++) {
            A0h[k] = __floats2half2_rn(__ldg(&A1[k * 64 + c0]),
                                       __ldg(&A1[k * 64 + c0 + 1]));
            A1h[k] = __floats2half2_rn(__ldg(&A1[512 + k * 64 + c0]),
                                       __ldg(&A1[512 + k * 64 + c0 + 1]));
            Bh[k]  = __floats2half2_rn(__ldg(&b1[k * 64 + c0]),
                                       __ldg(&b1[k * 64 + c0 + 1]));
        }

        const int gw = (blockIdx.x * blockDim.x + threadIdx.x) >> 5;
        const int nw = (GA_EDGE * blockDim.x) >> 5;

        for (int e0 = gw * 2; e0 < E; e0 += nw * 2) {
#pragma unroll
            for (int u = 0; u < 2; u++) {
                int e = e0 + u;
                if (e >= E) break;
                int src = clamp_idx(__ldg(&ei[e]), N);
                int dst = clamp_idx(__ldg(&ei[E + e]), N);
                float2 a = __ldg(reinterpret_cast<const float2*>(ea) + e);
                __half2 a0h = __float2half2_rn(a.x);
                __half2 a1h = __float2half2_rn(a.y);

                float xv = (lane < C1_IN) ? __ldg(&x[src * C1_IN + lane]) : 0.0f;
                unsigned int xu = u_of(__float2half2_rn(xv));  // (x,x) as half2

                __half2 acc = __float2half2_rn(0.0f);
#pragma unroll
                for (int k = 0; k < 8; k++) {
                    unsigned int xk = __shfl_sync(0xffffffffu, xu, k);
                    __half2 w = __hfma2(a0h, A0h[k], Bh[k]);
                    w = __hfma2_relu(a1h, A1h[k], w);
                    acc = __hfma2(w, h2_of(xk), acc);
                }
                red_h2(g_h16 + (size_t)dst * 32 + lane, acc);
            }
        }
    } else {
        // node1 role: g_h16[n, op] += (bias1 + x[n,:] @ root1) cols (2op,2op+1)
        int nblk = gridDim.x - GA_EDGE;
        int id = (blockIdx.x - GA_EDGE) * blockDim.x + threadIdx.x;
        int stride = nblk * blockDim.x;
        for (int p = id; p < N * 32; p += stride) {
            int n = p >> 5, op = p & 31;
            const float* xr = x + n * C1_IN;
            float acc0 = __ldg(&bias1[2 * op]);
            float acc1 = __ldg(&bias1[2 * op + 1]);
#pragma unroll
            for (int i = 0; i < C1_IN; i++) {
                float xv = __ldg(&xr[i]);
                acc0 = fmaf(xv, __ldg(&root1[i * 64 + 2 * op]), acc0);
                acc1 = fmaf(xv, __ldg(&root1[i * 64 + 2 * op + 1]), acc1);
            }
            red_f16x2(g_h16 + (size_t)n * 32 + op, acc0, acc1);
        }
    }
}

// ---------------------------------------------------------------------------
// Kernel B: fused layer-2 -> out (zeroed beforehand).
// Blocks [0, GB_EDGE): edge2 fp16 HFMA2 fused-relu, 2-edge interleave.
// Rest: node2 root term (fp32 math, streamed h row to keep regs low).
// ---------------------------------------------------------------------------
__global__ __launch_bounds__(128, 5)
void k_B(const int* __restrict__ ei,
         const float* __restrict__ ea,
         const float* __restrict__ A2,
         const float* __restrict__ b2,
         const float* __restrict__ root2,
         const float* __restrict__ bias2,
         float* __restrict__ out,
         int E, int N, int GB_EDGE)
{
    __shared__ __align__(16) __half2 hs[2][EPB][32];
    __shared__ __half2 sA0[2][EPB], sA1[2][EPB];
    __shared__ int     sDst[2][EPB];
    __shared__ __align__(16) float r2[4096];

    const int tid = threadIdx.x;

    if (blockIdx.x < GB_EDGE) {
        const int warp = tid >> 5;
        const int lane = tid & 31;
        const int col  = warp * 16 + (lane & 15);
        const int g    = lane >> 4;      // k half: [g*32, g*32+32)
        const int kbase = g * 32;

        // fp16x2 weight cache: 16 k-pairs for this (col, g): 48 regs.
        __half2 A0h[16], A1h[16], Bh[16];
#pragma unroll
        for (int kk = 0; kk < 16; kk++) {
            int k0 = kbase + 2 * kk;
            A0h[kk] = __floats2half2_rn(__ldg(&A2[k0 * 64 + col]),
                                        __ldg(&A2[(k0 + 1) * 64 + col]));
            A1h[kk] = __floats2half2_rn(__ldg(&A2[4096 + k0 * 64 + col]),
                                        __ldg(&A2[4096 + (k0 + 1) * 64 + col]));
            Bh[kk]  = __floats2half2_rn(__ldg(&b2[k0 * 64 + col]),
                                        __ldg(&b2[(k0 + 1) * 64 + col]));
        }

        const int nbatch = (E + EPB - 1) / EPB;

        // 16 rows x 8 uint4 (row = 32 half2 = 128B) = 128 uint4; one per thread.
        auto load_batch = [&](int b, int buf) {
            int row = tid >> 3, q = tid & 7;
            int e = b * EPB + row;
            int src = 0;
            if (e < E) src = clamp_idx(__ldg(&ei[e]), N);
            uint4 v = *reinterpret_cast<const uint4*>(
                g_h16 + (size_t)src * 32 + q * 4);
            *reinterpret_cast<uint4*>(&hs[buf][row][q * 4]) = v;
            if (tid < EPB) {
                int em = b * EPB + tid;
                float2 a = make_float2(0.0f, 0.0f);
                int dst = 0;
                if (em < E) {
                    a = __ldg(reinterpret_cast<const float2*>(ea) + em);
                    dst = clamp_idx(__ldg(&ei[E + em]), N);
                }
                sA0[buf][tid] = __float2half2_rn(a.x);
                sA1[buf][tid] = __float2half2_rn(a.y);
                sDst[buf][tid] = dst;
            }
        };

        int b = blockIdx.x;
        int buf = 0;
        if (b < nbatch) load_batch(b, 0);
        __syncthreads();

        while (b < nbatch) {
            int bn = b + GB_EDGE;
            if (bn < nbatch) load_batch(bn, buf ^ 1);

            int e0 = b * EPB;
#pragma unroll 2
            for (int j = 0; j < EPB; j += 2) {
                __half2 a0A = sA0[buf][j],     a1A = sA1[buf][j];
                __half2 a0B = sA0[buf][j + 1], a1B = sA1[buf][j + 1];
                const uint4* hpA = reinterpret_cast<const uint4*>(&hs[buf][j][g * 16]);
                const uint4* hpB = reinterpret_cast<const uint4*>(&hs[buf][j + 1][g * 16]);

                __half2 zero = __float2half2_rn(0.0f);
                __half2 accA0 = zero, accA1 = zero, accB0 = zero, accB1 = zero;
#pragma unroll
                for (int t = 0; t < 4; t++) {
                    uint4 hA = hpA[t];   // 4 half2 = 4 k-pairs (LDS.128)
                    uint4 hB = hpB[t];
                    __half2 w;
                    w = __hfma2(a0A, A0h[4 * t + 0], Bh[4 * t + 0]);
                    w = __hfma2_relu(a1A, A1h[4 * t + 0], w);
                    accA0 = __hfma2(w, h2_of(hA.x), accA0);
                    w = __hfma2(a0B, A0h[4 * t + 0], Bh[4 * t + 0]);
                    w = __hfma2_relu(a1B, A1h[4 * t + 0], w);
                    accB0 = __hfma2(w, h2_of(hB.x), accB0);

                    w = __hfma2(a0A, A0h[4 * t + 1], Bh[4 * t + 1]);
                    w = __hfma2_relu(a1A, A1h[4 * t + 1], w);
                    accA1 = __hfma2(w, h2_of(hA.y), accA1);
                    w = __hfma2(a0B, A0h[4 * t + 1], Bh[4 * t + 1]);
                    w = __hfma2_relu(a1B, A1h[4 * t + 1], w);
                    accB1 = __hfma2(w, h2_of(hB.y), accB1);

                    w = __hfma2(a0A, A0h[4 * t + 2], Bh[4 * t + 2]);
                    w = __hfma2_relu(a1A, A1h[4 * t + 2], w);
                    accA0 = __hfma2(w, h2_of(hA.z), accA0);
                    w = __hfma2(a0B, A0h[4 * t + 2], Bh[4 * t + 2]);
                    w = __hfma2_relu(a1B, A1h[4 * t + 2], w);
                    accB0 = __hfma2(w, h2_of(hB.z), accB0);

                    w = __hfma2(a0A, A0h[4 * t + 3], Bh[4 * t + 3]);
                    w = __hfma2_relu(a1A, A1h[4 * t + 3], w);
                    accA1 = __hfma2(w, h2_of(hA.w), accA1);
                    w = __hfma2(a0B, A0h[4 * t + 3], Bh[4 * t + 3]);
                    w = __hfma2_relu(a1B, A1h[4 * t + 3], w);
                    accB1 = __hfma2(w, h2_of(hB.w), accB1);
                }
                // Epilogues for both edges.
                {
                    __half2 s = __hadd2(accA0, accA1);
                    float2 f = __half22float2(s);
                    float acc = f.x + f.y;
                    acc += __shfl_xor_sync(0xffffffffu, acc, 16);
                    if (g == 0 && (e0 + j) < E) {
                        float* p = out + (size_t)sDst[buf][j] * 64 + col;
                        asm volatile("red.global.add.f32 [%0], %1;"
                                     :: "l"(p), "f"(acc) : "memory");
                    }
                }
                {
                    __half2 s = __hadd2(accB0, accB1);
                    float2 f = __half22float2(s);
                    float acc = f.x + f.y;
                    acc += __shfl_xor_sync(0xffffffffu, acc, 16);
                    if (g == 0 && (e0 + j + 1) < E) {
                        float* p = out + (size_t)sDst[buf][j + 1] * 64 + col;
                        asm volatile("red.global.add.f32 [%0], %1;"
                                     :: "l"(p), "f"(acc) : "memory");
                    }
                }
            }
            __syncthreads();
            buf ^= 1;
            b = bn;
        }
    } else {
        // node2 role: out[n, 2op..2op+1] += bias2 + h[n,:] @ root2.
        // Streamed: consume each uint4 of the h row immediately (low reg count).
        for (int i = tid; i < 4096; i += 128)
            r2[i] = __ldg(&root2[i]);
        __syncthreads();

        const int op = tid & 31;
        const int j  = tid >> 5;   // 0..3
        float2 bv = __ldg(reinterpret_cast<const float2*>(bias2) + op);
        const unsigned long long bp = pk2(bv.x, bv.y);
        const unsigned long long* r2p =
            reinterpret_cast<const unsigned long long*>(r2);

        int nblk = gridDim.x - GB_EDGE;
        for (int nb = (blockIdx.x - GB_EDGE) * 4; nb < N; nb += nblk * 4) {
            int n = nb + j;
            const uint4* hr = reinterpret_cast<const uint4*>(g_h16 + (size_t)n * 32);
            unsigned long long acc = bp;
#pragma unroll
            for (int t = 0; t < 8; t++) {
                uint4 v = hr[t];   // 4 half2 = k values 8t .. 8t+7
                unsigned int vw[4];
                *reinterpret_cast<uint4*>(vw) = v;
#pragma unroll
                for (int u = 0; u < 4; u++) {
                    float2 f = __half22float2(h2_of(vw[u]));
                    acc = ffma2(pk2(f.x, f.x), r2p[(8 * t + 2 * u) * 32 + op], acc);
                    acc = ffma2(pk2(f.y, f.y), r2p[(8 * t + 2 * u + 1) * 32 + op], acc);
                }
            }
            float ol, oh;
            upk2(acc, ol, oh);
            float* po = out + (size_t)n * 64 + 2 * op;
            asm volatile("red.global.add.v2.f32 [%0], {%1, %2};"
                         :: "l"(po), "f"(ol), "f"(oh) : "memory");
        }
    }
}

// ---------------------------------------------------------------------------
// Launch
// ---------------------------------------------------------------------------
extern "C" void kernel_launch(void* const* d_in, const int* in_sizes, int n_in,
                              void* d_out, int out_size)
{
    const float* x     = (const float*)d_in[0];
    const int*   ei    = (const int*)d_in[1];
    const float* ea    = (const float*)d_in[2];
    const float* A1    = (const float*)d_in[3];
    const float* b1    = (const float*)d_in[4];
    const float* A2    = (const float*)d_in[5];
    const float* b2    = (const float*)d_in[6];
    const float* root1 = (const float*)d_in[7];
    const float* bias1 = (const float*)d_in[8];
    const float* root2 = (const float*)d_in[9];
    const float* bias2 = (const float*)d_in[10];
    float* out = (float*)d_out;

    const int N = in_sizes[0] / C1_IN;   // 16384
    const int E = in_sizes[1] / 2;       // 65536

    void* hptr = nullptr;
    cudaGetSymbolAddress(&hptr, g_h16);
    cudaMemsetAsync(hptr, 0, (size_t)NN * 32 * sizeof(__half2));
    cudaMemsetAsync(out, 0, (size_t)out_size * sizeof(float));

    const int GA_EDGE = 592;
    k_A<<<GA_EDGE + 296, 256>>>(x, ei, ea, A1, b1, root1, bias1, E, N, GA_EDGE);

    const int GB_EDGE = 740;
    k_B<<<GB_EDGE + 296, 128>>>(ei, ea, A2, b2, root2, bias2, out, E, N, GB_EDGE);
}